// round 16
// baseline (speedup 1.0000x reference)
#include <cuda_runtime.h>
#include <cstdint>

#define Nn 10000
#define Cc 128
#define Hh 256
#define Ee 320000

constexpr float kCutoff = 5.0f;
constexpr float kEps    = 1e-5f;
constexpr float kPi     = 3.14159265358979323846f;

// ---------------- scratch (device globals; no runtime allocation) ----------------
__device__ float    g_hn   [Nn * Cc];    // LN1(h) exact (residual path)
__device__ uint32_t g_hn_tf[Nn * Cc];    // LN1(h) tf32 (GEMM A)
__device__ float    g_P12  [Nn * 512];   // [P1 | P2] node projections
__device__ float    g_sums [Nn * Hh];    // segment sums
__device__ float    g_cnt  [Nn];         // segment counts
__device__ uint32_t g_ma_tf[Nn * Hh];    // m_aggr tf32
__device__ uint32_t g_t    [Nn * Hh];    // node MLP hidden (tf32)
__device__ float    g_h1   [Nn * Cc];
__device__ uint32_t g_h2_tf[Nn * Cc];    // LN2(h1) tf32
__device__ uint32_t g_u    [Nn * Hh];    // out MLP hidden (tf32)
// tf32 weights
// We2 pair-permuted: idx = (k>>3)*2048 + (k&3)*512 + n*2 + ((k>>2)&1)
__device__ uint32_t g_We2p [Hh * Hh];
__device__ uint32_t g_We1tf[Cc * 512];       // [k][n'] n'<256: We1[k][n'], else We1[k+128][n'-256]
__device__ uint32_t g_Wn1tf[(Cc + Hh) * Hh]; // 384x256
__device__ uint32_t g_Wn2tf[Hh * Cc];        // 256x128
__device__ uint32_t g_Wm1tf[Cc * Hh];        // 128x256
__device__ uint32_t g_Wm2tf[Hh * Cc];        // 256x128

__device__ __forceinline__ float silu_f(float v) {
    return v * (1.0f / (1.0f + __expf(-v)));
}
__device__ __forceinline__ uint32_t f2tf32(float f) {
    uint32_t r; asm("cvt.rna.tf32.f32 %0, %1;" : "=r"(r) : "f"(f)); return r;
}
__device__ __forceinline__ void cp_async16(uint32_t dst, const void* src) {
    asm volatile("cp.async.ca.shared.global [%0], [%1], 16;"
                 :: "r"(dst), "l"(src) : "memory");
}
__device__ __forceinline__ void mma_tf32(float& c0, float& c1, float& c2, float& c3,
                                         uint32_t a0, uint32_t a1, uint32_t a2, uint32_t a3,
                                         uint32_t b0, uint32_t b1) {
    asm volatile(
        "mma.sync.aligned.m16n8k8.row.col.f32.tf32.tf32.f32 "
        "{%0,%1,%2,%3}, {%4,%5,%6,%7}, {%8,%9}, {%0,%1,%2,%3};"
        : "+f"(c0), "+f"(c1), "+f"(c2), "+f"(c3)
        : "r"(a0), "r"(a1), "r"(a2), "r"(a3), "r"(b0), "r"(b1));
}

// ---------------- weights -> tf32 once ----------------
__global__ void prepW_kernel(const float* __restrict__ We2, const float* __restrict__ Wn1,
                             const float* __restrict__ Wn2, const float* __restrict__ Wm1,
                             const float* __restrict__ Wm2, const float* __restrict__ We1) {
    int i = blockIdx.x * 256 + threadIdx.x;
    if (i < Hh * Hh) {
        int k = i >> 8, n = i & 255;
        int dst = (k >> 3) * 2048 + (k & 3) * 512 + n * 2 + ((k >> 2) & 1);
        g_We2p[dst] = f2tf32(We2[i]);
    }
    if (i < (Cc + Hh) * Hh) g_Wn1tf[i] = f2tf32(Wn1[i]);
    if (i < Hh * Cc) {
        g_Wn2tf[i] = f2tf32(Wn2[i]);
        g_Wm1tf[i] = f2tf32(Wm1[i]);
        g_Wm2tf[i] = f2tf32(Wm2[i]);
    }
    if (i < Cc * 512) {
        int k = i >> 9, n = i & 511;
        float v = (n < 256) ? We1[k * Hh + n] : We1[(k + 128) * Hh + (n - 256)];
        g_We1tf[i] = f2tf32(v);
    }
}

// ---------------- LayerNorm over C=128, one block per row ----------------
// WHICH==0 also zeroes g_sums / g_cnt (graph replays must reset them).
template<int WHICH>   // 0: h -> g_hn + g_hn_tf ; 1: g_h1 -> g_h2_tf
__global__ void ln_kernel(const float* __restrict__ in,
                          const float* __restrict__ gg,
                          const float* __restrict__ bb) {
    int n = blockIdx.x, c = threadIdx.x;
    if (WHICH == 0) {
        g_sums[n * Hh + c]       = 0.0f;
        g_sums[n * Hh + 128 + c] = 0.0f;
        if (c == 0) g_cnt[n] = 0.0f;
    }
    const float* src = (WHICH == 0) ? in : g_h1;
    float v = src[n * Cc + c];
    float s = v, s2 = v * v;
    #pragma unroll
    for (int o = 16; o; o >>= 1) {
        s  += __shfl_xor_sync(0xffffffffu, s,  o);
        s2 += __shfl_xor_sync(0xffffffffu, s2, o);
    }
    __shared__ float ws[4], ws2[4];
    if ((c & 31) == 0) { ws[c >> 5] = s; ws2[c >> 5] = s2; }
    __syncthreads();
    s  = ws[0]  + ws[1]  + ws[2]  + ws[3];
    s2 = ws2[0] + ws2[1] + ws2[2] + ws2[3];
    float mu  = s * (1.0f / Cc);
    float var = s2 * (1.0f / Cc) - mu * mu;
    float o = (v - mu) * rsqrtf(var + kEps) * gg[c] + bb[c];
    if (WHICH == 0) {
        g_hn[n * Cc + c]    = o;
        g_hn_tf[n * Cc + c] = f2tf32(o);
    } else {
        g_h2_tf[n * Cc + c] = f2tf32(o);
    }
}

// ---------------- m_aggr -> tf32 ----------------
__global__ void magg_kernel() {
    int n = blockIdx.x, k = threadIdx.x;
    float inv = 1.0f / fmaxf(g_cnt[n], 1.0f);
    g_ma_tf[n * Hh + k] = f2tf32(g_sums[n * Hh + k] * inv);
}

// ---------------- generic node GEMM on mma.sync tf32 ----------------
enum { M_P1P2 = 0, M_NMLP1 = 1, M_NMLP2 = 2, M_MMLP1 = 3, M_MMLP2 = 4 };
#define BSTN 136   // B smem row stride (u32)

template<int K, int NCOLS, int MODE>
__global__ void __launch_bounds__(256) node_gemm(const float* __restrict__ bias,
                                                 const float* __restrict__ res1,
                                                 float* __restrict__ out_h) {
    const uint32_t* A0;  const uint32_t* A1 = nullptr;
    const uint32_t* Btf; float* outf = nullptr; uint32_t* outu = nullptr;
    if constexpr (MODE == M_P1P2)  { A0 = g_hn_tf; Btf = g_We1tf; outf = g_P12; }
    if constexpr (MODE == M_NMLP1) { A0 = g_hn_tf; A1 = g_ma_tf; Btf = g_Wn1tf; outu = g_t; }
    if constexpr (MODE == M_NMLP2) { A0 = g_t;     Btf = g_Wn2tf; outf = g_h1; }
    if constexpr (MODE == M_MMLP1) { A0 = g_h2_tf; Btf = g_Wm1tf; outu = g_u; }
    if constexpr (MODE == M_MMLP2) { A0 = g_u;     Btf = g_Wm2tf; outf = out_h; }
    constexpr int KA0 = (MODE == M_NMLP1) ? 128 : K;
    constexpr int NCH = K / 16;

    __shared__ __align__(16) uint32_t Bs[2][16 * BSTN];
    int tid = threadIdx.x, lane = tid & 31, w = tid >> 5;
    int wm = w & 1, wn = w >> 1;
    int rbase = blockIdx.x * 64;
    int cbase = blockIdx.y * 128;
    uint32_t sB[2] = { (uint32_t)__cvta_generic_to_shared(Bs[0]),
                       (uint32_t)__cvta_generic_to_shared(Bs[1]) };

    #pragma unroll
    for (int i = 0; i < 2; i++) {
        int idx4 = tid + i * 256;
        int k = idx4 >> 5, n4 = (idx4 & 31) << 2;
        cp_async16(sB[0] + (k * BSTN + n4) * 4, Btf + k * NCOLS + cbase + n4);
    }
    asm volatile("cp.async.commit_group;\n\tcp.async.wait_group 0;" ::: "memory");
    __syncthreads();

    float acc[2][4][4];
    #pragma unroll
    for (int mt = 0; mt < 2; mt++)
        #pragma unroll
        for (int nt = 0; nt < 4; nt++)
            #pragma unroll
            for (int q = 0; q < 4; q++) acc[mt][nt][q] = 0.0f;

    int rc[2][2];
    #pragma unroll
    for (int mt = 0; mt < 2; mt++) {
        rc[mt][0] = min(rbase + 32 * wm + 16 * mt + (lane >> 2), Nn - 1);
        rc[mt][1] = min(rbase + 32 * wm + 16 * mt + (lane >> 2) + 8, Nn - 1);
    }
    int bq = 32 * wn + (lane >> 2);

    #pragma unroll 1
    for (int kc = 0; kc < NCH; kc++) {
        if (kc < NCH - 1) {
            const uint32_t* src = Btf + (kc + 1) * 16 * NCOLS + cbase;
            uint32_t d = sB[(kc + 1) & 1];
            #pragma unroll
            for (int i = 0; i < 2; i++) {
                int idx4 = tid + i * 256;
                int k = idx4 >> 5, n4 = (idx4 & 31) << 2;
                cp_async16(d + (k * BSTN + n4) * 4, src + k * NCOLS + n4);
            }
            asm volatile("cp.async.commit_group;" ::: "memory");
        }
        const uint32_t* Bw = Bs[kc & 1] + (lane & 3) * BSTN + bq;
        #pragma unroll
        for (int st = 0; st < 2; st++) {
            int kk = kc * 16 + st * 8 + (lane & 3);
            uint32_t a[2][4];
            #pragma unroll
            for (int mt = 0; mt < 2; mt++) {
                const uint32_t *pa0, *pa1;
                if (MODE == M_NMLP1 && kk >= 128) {
                    pa0 = A1 + rc[mt][0] * Hh + (kk - 128);
                    pa1 = A1 + rc[mt][1] * Hh + (kk - 128);
                } else {
                    pa0 = A0 + rc[mt][0] * KA0 + kk;
                    pa1 = A0 + rc[mt][1] * KA0 + kk;
                }
                a[mt][0] = pa0[0]; a[mt][1] = pa1[0];
                a[mt][2] = pa0[4]; a[mt][3] = pa1[4];
            }
            uint32_t b[4][2];
            const uint32_t* Bb = Bw + st * 8 * BSTN;
            #pragma unroll
            for (int nt = 0; nt < 4; nt++) {
                b[nt][0] = Bb[8 * nt];
                b[nt][1] = Bb[4 * BSTN + 8 * nt];
            }
            #pragma unroll
            for (int mt = 0; mt < 2; mt++)
                #pragma unroll
                for (int nt = 0; nt < 4; nt++)
                    mma_tf32(acc[mt][nt][0], acc[mt][nt][1], acc[mt][nt][2], acc[mt][nt][3],
                             a[mt][0], a[mt][1], a[mt][2], a[mt][3], b[nt][0], b[nt][1]);
        }
        if (kc < NCH - 1) asm volatile("cp.async.wait_group 0;" ::: "memory");
        __syncthreads();
    }

    #pragma unroll
    for (int mt = 0; mt < 2; mt++) {
        int r0 = rbase + 32 * wm + 16 * mt + (lane >> 2);
        int r1r = r0 + 8;
        #pragma unroll
        for (int nt = 0; nt < 4; nt++) {
            int col = cbase + 32 * wn + 8 * nt + 2 * (lane & 3);
            #pragma unroll
            for (int q = 0; q < 4; q++) {
                int r  = (q < 2) ? r0 : r1r;
                int cg = col + (q & 1);
                if (r < Nn) {
                    float v = acc[mt][nt][q];
                    if constexpr (MODE == M_P1P2) {
                        outf[r * NCOLS + cg] = v;
                    } else if constexpr (MODE == M_NMLP1 || MODE == M_MMLP1) {
                        outu[r * NCOLS + cg] = f2tf32(silu_f(v + bias[cg]));
                    } else if constexpr (MODE == M_NMLP2) {
                        outf[r * NCOLS + cg] = res1[r * NCOLS + cg] + g_hn[r * NCOLS + cg]
                                             + v + bias[cg];
                    } else {   // M_MMLP2
                        outf[r * NCOLS + cg] = g_h1[r * NCOLS + cg] + v + bias[cg];
                    }
                }
            }
        }
    }
}

// ---------------- edge kernel: pair-interleaved smem + LDS.64 frags + pipelined mainloop ----
#define EPB  64                 // edges per CTA (GEMM M)
#define KC   16                 // K-chunk rows
#define ASTA 264                // A smem row stride (u32), 264 % 32 == 8
#define BSTB 520                // B smem kq-row stride (u32), 520 % 32 == 8
constexpr int A_SMEM_U32 = EPB * ASTA;       // 16896
constexpr int B_SMEM_U32 = 8 * BSTB;         // 4160 per chunk buffer
constexpr int EDGE_DSMEM = (A_SMEM_U32 + 2 * B_SMEM_U32) * 4;   // 100864 B

__global__ void __launch_bounds__(256, 2) edge_kernel(const float* __restrict__ x,
                                                      const int*   __restrict__ eidx,
                                                      const float* __restrict__ We1,
                                                      const float* __restrict__ be1,
                                                      const float* __restrict__ be2) {
    extern __shared__ __align__(16) uint32_t dynbuf[];
    uint32_t* As = dynbuf;                         // [64][ASTA] pair-interleaved
    uint32_t* Bs[2] = { dynbuf + A_SMEM_U32,
                        dynbuf + A_SMEM_U32 + B_SMEM_U32 };

    __shared__ float sDist[EPB], sCcut[EPB], sWl[Hh], sBe1[Hh], sBe2[Hh];
    __shared__ int   sRow[EPB], sCol[EPB];

    int tid  = threadIdx.x;
    int lane = tid & 31;
    int w    = tid >> 5;
    int wm   = w & 1;
    int wn   = w >> 1;
    int e0   = blockIdx.x * EPB;

    uint32_t sBu[2];
    sBu[0] = (uint32_t)__cvta_generic_to_shared(Bs[0]);
    sBu[1] = (uint32_t)__cvta_generic_to_shared(Bs[1]);

    // stage B chunk 0 (pair-permuted global layout; 8 rows x 512 u32)
    {
        #pragma unroll
        for (int i = 0; i < 4; i++) {
            int idx4 = tid + i * 256;          // 0..1023
            int rr   = idx4 >> 7;              // 0..7
            int off4 = idx4 & 127;
            cp_async16(sBu[0] + (rr * BSTB + off4 * 4) * 4,
                       g_We2p + rr * 512 + off4 * 4);
        }
        asm volatile("cp.async.commit_group;" ::: "memory");
    }

    if (tid < EPB) {
        int e = e0 + tid;
        int r = eidx[e];
        int c = eidx[Ee + e];
        sRow[tid] = r;
        sCol[tid] = c;
        float dx = x[r * 3 + 0] - x[c * 3 + 0];
        float dy = x[r * 3 + 1] - x[c * 3 + 1];
        float dz = x[r * 3 + 2] - x[c * 3 + 2];
        float d  = sqrtf(dx * dx + dy * dy + dz * dz);
        sDist[tid] = d;
        float cc = 0.5f * (__cosf(d * (kPi / kCutoff)) + 1.0f);
        sCcut[tid] = (d <= kCutoff) ? cc : 0.0f;
        atomicAdd(&g_cnt[c], 1.0f);
    }
    sWl[tid]  = We1[(2 * Cc) * Hh + tid];
    sBe1[tid] = be1[tid];
    sBe2[tid] = be2[tid];
    __syncthreads();

    // ---- A tile: silu(P1[row]+P2[col]+d*wl+b1) -> tf32, pair-interleaved:
    // lane owns cols 8L..8L+7; smem[e*ASTA + L*8 + (c&3)*2 + ((c>>2)&1)]
    #pragma unroll 2
    for (int ei = 0; ei < 8; ei++) {
        int e = w * 8 + ei;
        float d = sDist[e];
        const float4* p1 = (const float4*)(g_P12 + sRow[e] * 512);
        const float4* p2 = (const float4*)(g_P12 + sCol[e] * 512 + 256);
        float4 x0 = p1[2 * lane], x1 = p1[2 * lane + 1];
        float4 y0 = p2[2 * lane], y1 = p2[2 * lane + 1];
        float4 w0 = ((const float4*)sWl)[2 * lane],  w1 = ((const float4*)sWl)[2 * lane + 1];
        float4 c0 = ((const float4*)sBe1)[2 * lane], c1 = ((const float4*)sBe1)[2 * lane + 1];
        uint4 o0, o1;
        o0.x = f2tf32(silu_f(x0.x + y0.x + d * w0.x + c0.x));   // col+0
        o0.y = f2tf32(silu_f(x1.x + y1.x + d * w1.x + c1.x));   // col+4
        o0.z = f2tf32(silu_f(x0.y + y0.y + d * w0.y + c0.y));   // col+1
        o0.w = f2tf32(silu_f(x1.y + y1.y + d * w1.y + c1.y));   // col+5
        o1.x = f2tf32(silu_f(x0.z + y0.z + d * w0.z + c0.z));   // col+2
        o1.y = f2tf32(silu_f(x1.z + y1.z + d * w1.z + c1.z));   // col+6
        o1.z = f2tf32(silu_f(x0.w + y0.w + d * w0.w + c0.w));   // col+3
        o1.w = f2tf32(silu_f(x1.w + y1.w + d * w1.w + c1.w));   // col+7
        *(uint4*)(As + e * ASTA + lane * 8)     = o0;
        *(uint4*)(As + e * ASTA + lane * 8 + 4) = o1;
    }
    asm volatile("cp.async.wait_group 0;" ::: "memory");
    __syncthreads();

    float acc[2][8][4];
    #pragma unroll
    for (int mt = 0; mt < 2; mt++)
        #pragma unroll
        for (int nt = 0; nt < 8; nt++)
            #pragma unroll
            for (int q = 0; q < 4; q++) acc[mt][nt][q] = 0.0f;

    int ar0 = 32 * wm + (lane >> 2);
    int bq0 = 64 * wn + (lane >> 2);
    const uint32_t* Aw = As + ar0 * ASTA + (lane & 3) * 2;

    uint2 bf0[8], bf1[8];

    // B frag load: pair (k, k+4) adjacent; row = st*4 + (lane&3)
    #define LDB(bf, buf, st)                                                     \
        {                                                                        \
            const uint32_t* p_ = Bs[buf] + ((st) * 4 + (lane & 3)) * BSTB + bq0 * 2; \
            _Pragma("unroll")                                                    \
            for (int nt_ = 0; nt_ < 8; nt_++)                                    \
                bf[nt_] = *(const uint2*)(p_ + nt_ * 16);                        \
        }

    #define LDA_MMA(bf, kc, st)                                                  \
        {                                                                        \
            const uint32_t* Ab_ = Aw + ((kc) * 2 + (st)) * 8;                    \
            uint2 a00 = *(const uint2*)(Ab_);                                    \
            uint2 a01 = *(const uint2*)(Ab_ + 8 * ASTA);                         \
            uint2 a10 = *(const uint2*)(Ab_ + 16 * ASTA);                        \
            uint2 a11 = *(const uint2*)(Ab_ + 24 * ASTA);                        \
            _Pragma("unroll")                                                    \
            for (int nt_ = 0; nt_ < 8; nt_++) {                                  \
                mma_tf32(acc[0][nt_][0], acc[0][nt_][1], acc[0][nt_][2], acc[0][nt_][3], \
                         a00.x, a01.x, a00.y, a01.y, bf[nt_].x, bf[nt_].y);      \
                mma_tf32(acc[1][nt_][0], acc[1][nt_][1], acc[1][nt_][2], acc[1][nt_][3], \
                         a10.x, a11.x, a10.y, a11.y, bf[nt_].x, bf[nt_].y);      \
            }                                                                    \
        }

    LDB(bf0, 0, 0);
    #pragma unroll 1
    for (int kc = 0; kc < 16; kc++) {
        if (kc < 15) {
            const uint32_t* src = g_We2p + (kc + 1) * 4096;
            uint32_t dstb = sBu[(kc + 1) & 1];
            #pragma unroll
            for (int i = 0; i < 4; i++) {
                int idx4 = tid + i * 256;
                int rr   = idx4 >> 7;
                int off4 = idx4 & 127;
                cp_async16(dstb + (rr * BSTB + off4 * 4) * 4, src + rr * 512 + off4 * 4);
            }
            asm volatile("cp.async.commit_group;" ::: "memory");
        }
        LDB(bf1, kc & 1, 1);
        LDA_MMA(bf0, kc, 0);
        if (kc < 15) asm volatile("cp.async.wait_group 0;" ::: "memory");
        __syncthreads();
        if (kc < 15) LDB(bf0, (kc + 1) & 1, 0);
        LDA_MMA(bf1, kc, 1);
    }

    // ---- epilogue: +bias, silu, *cutoff, scatter-add
    #pragma unroll
    for (int mt = 0; mt < 2; mt++) {
        int r0 = 32 * wm + 16 * mt + (lane >> 2);
        int r1 = r0 + 8;
        float cc0 = sCcut[r0], cc1 = sCcut[r1];
        int base0 = sCol[r0] * Hh, base1 = sCol[r1] * Hh;
        #pragma unroll
        for (int nt = 0; nt < 8; nt++) {
            int col = 64 * wn + 8 * nt + 2 * (lane & 3);
            float b0 = sBe2[col], b1 = sBe2[col + 1];
            atomicAdd(&g_sums[base0 + col],     silu_f(acc[0 + mt * 0][nt][0] * 0.0f + acc[mt][nt][0] + b0) * cc0);
            atomicAdd(&g_sums[base0 + col + 1], silu_f(acc[mt][nt][1] + b1) * cc0);
            atomicAdd(&g_sums[base1 + col],     silu_f(acc[mt][nt][2] + b0) * cc1);
            atomicAdd(&g_sums[base1 + col + 1], silu_f(acc[mt][nt][3] + b1) * cc1);
        }
    }
}

// ---------------- launch ----------------
extern "C" void kernel_launch(void* const* d_in, const int* in_sizes, int n_in,
                              void* d_out, int out_size) {
    const float* x     = (const float*)d_in[0];
    const float* h     = (const float*)d_in[1];
    const int*   eidx  = (const int*)  d_in[2];
    const float* We1   = (const float*)d_in[3];
    const float* be1   = (const float*)d_in[4];
    const float* We2   = (const float*)d_in[5];
    const float* be2   = (const float*)d_in[6];
    const float* Wn1   = (const float*)d_in[7];
    const float* bn1   = (const float*)d_in[8];
    const float* Wn2   = (const float*)d_in[9];
    const float* bn2   = (const float*)d_in[10];
    const float* Wm1   = (const float*)d_in[11];
    const float* bm1   = (const float*)d_in[12];
    const float* Wm2   = (const float*)d_in[13];
    const float* bm2   = (const float*)d_in[14];
    const float* g1    = (const float*)d_in[15];
    const float* beta1 = (const float*)d_in[16];
    const float* g2    = (const float*)d_in[17];
    const float* beta2 = (const float*)d_in[18];

    static int attr_done = 0;
    if (!attr_done) {
        cudaFuncSetAttribute(edge_kernel,
                             cudaFuncAttributeMaxDynamicSharedMemorySize, EDGE_DSMEM);
        attr_done = 1;
    }

    const int RB = (Nn + 63) / 64;   // 157

    // NOTE: edge_kernel is intentionally launch #4 (ncu samples the 4th launch).
    prepW_kernel<<<((Cc + Hh) * Hh + 255) / 256, 256>>>(We2, Wn1, Wn2, Wm1, Wm2, We1);
    ln_kernel<0><<<Nn, Cc>>>(h, g1, beta1);                               // also zeroes sums/cnt
    node_gemm<128, 512, M_P1P2><<<dim3(RB, 4), 256>>>(nullptr, nullptr, nullptr);
    edge_kernel<<<Ee / EPB, 256, EDGE_DSMEM>>>(x, eidx, We1, be1, be2);
    magg_kernel<<<Nn, Hh>>>();
    node_gemm<384, 256, M_NMLP1><<<dim3(RB, 2), 256>>>(bn1, nullptr, nullptr);
    node_gemm<256, 128, M_NMLP2><<<dim3(RB, 1), 256>>>(bn2, h, nullptr);
    ln_kernel<1><<<Nn, Cc>>>(h, g2, beta2);
    node_gemm<128, 256, M_MMLP1><<<dim3(RB, 2), 256>>>(bm1, nullptr, nullptr);
    node_gemm<256, 128, M_MMLP2><<<dim3(RB, 1), 256>>>(bm2, nullptr, (float*)d_out);
}

// round 17
// speedup vs baseline: 1.0013x; 1.0013x over previous
#include <cuda_runtime.h>
#include <cstdint>

#define Nn 10000
#define Cc 128
#define Hh 256
#define Ee 320000

constexpr float kCutoff = 5.0f;
constexpr float kEps    = 1e-5f;
constexpr float kPi     = 3.14159265358979323846f;

// ---------------- scratch (device globals; no runtime allocation) ----------------
__device__ float    g_hn   [Nn * Cc];    // LN1(h) exact (residual path)
__device__ uint32_t g_hn_tf[Nn * Cc];    // LN1(h) tf32 (GEMM A)
__device__ float    g_P12  [Nn * 512];   // [P1 | P2] node projections
__device__ float    g_sums [Nn * Hh];    // segment sums
__device__ float    g_cnt  [Nn];         // segment counts
__device__ uint32_t g_ma_tf[Nn * Hh];    // m_aggr tf32
__device__ uint32_t g_t    [Nn * Hh];    // node MLP hidden (tf32)
__device__ float    g_h1   [Nn * Cc];
__device__ uint32_t g_h2_tf[Nn * Cc];    // LN2(h1) tf32
__device__ uint32_t g_u    [Nn * Hh];    // out MLP hidden (tf32)
// tf32 weights
// We2 pair-permuted: idx = (k>>3)*2048 + (k&3)*512 + n*2 + ((k>>2)&1)
__device__ uint32_t g_We2p [Hh * Hh];
__device__ uint32_t g_We1tf[Cc * 512];       // [k][n'] n'<256: We1[k][n'], else We1[k+128][n'-256]
__device__ uint32_t g_Wn1tf[(Cc + Hh) * Hh]; // 384x256
__device__ uint32_t g_Wn2tf[Hh * Cc];        // 256x128
__device__ uint32_t g_Wm1tf[Cc * Hh];        // 128x256
__device__ uint32_t g_Wm2tf[Hh * Cc];        // 256x128

__device__ __forceinline__ float silu_f(float v) {
    return v * (1.0f / (1.0f + __expf(-v)));
}
__device__ __forceinline__ uint32_t f2tf32(float f) {
    uint32_t r; asm("cvt.rna.tf32.f32 %0, %1;" : "=r"(r) : "f"(f)); return r;
}
__device__ __forceinline__ void cp_async16(uint32_t dst, const void* src) {
    asm volatile("cp.async.ca.shared.global [%0], [%1], 16;"
                 :: "r"(dst), "l"(src) : "memory");
}
__device__ __forceinline__ void mma_tf32(float& c0, float& c1, float& c2, float& c3,
                                         uint32_t a0, uint32_t a1, uint32_t a2, uint32_t a3,
                                         uint32_t b0, uint32_t b1) {
    asm volatile(
        "mma.sync.aligned.m16n8k8.row.col.f32.tf32.tf32.f32 "
        "{%0,%1,%2,%3}, {%4,%5,%6,%7}, {%8,%9}, {%0,%1,%2,%3};"
        : "+f"(c0), "+f"(c1), "+f"(c2), "+f"(c3)
        : "r"(a0), "r"(a1), "r"(a2), "r"(a3), "r"(b0), "r"(b1));
}

// ---------------- weights -> tf32 once ----------------
__global__ void prepW_kernel(const float* __restrict__ We2, const float* __restrict__ Wn1,
                             const float* __restrict__ Wn2, const float* __restrict__ Wm1,
                             const float* __restrict__ Wm2, const float* __restrict__ We1) {
    int i = blockIdx.x * 256 + threadIdx.x;
    if (i < Hh * Hh) {
        int k = i >> 8, n = i & 255;
        int dst = (k >> 3) * 2048 + (k & 3) * 512 + n * 2 + ((k >> 2) & 1);
        g_We2p[dst] = f2tf32(We2[i]);
    }
    if (i < (Cc + Hh) * Hh) g_Wn1tf[i] = f2tf32(Wn1[i]);
    if (i < Hh * Cc) {
        g_Wn2tf[i] = f2tf32(Wn2[i]);
        g_Wm1tf[i] = f2tf32(Wm1[i]);
        g_Wm2tf[i] = f2tf32(Wm2[i]);
    }
    if (i < Cc * 512) {
        int k = i >> 9, n = i & 511;
        float v = (n < 256) ? We1[k * Hh + n] : We1[(k + 128) * Hh + (n - 256)];
        g_We1tf[i] = f2tf32(v);
    }
}

// ---------------- LayerNorm over C=128, one block per row ----------------
// WHICH==0 also zeroes g_sums / g_cnt (graph replays must reset them).
template<int WHICH>   // 0: h -> g_hn + g_hn_tf ; 1: g_h1 -> g_h2_tf
__global__ void ln_kernel(const float* __restrict__ in,
                          const float* __restrict__ gg,
                          const float* __restrict__ bb) {
    int n = blockIdx.x, c = threadIdx.x;
    if (WHICH == 0) {
        g_sums[n * Hh + c]       = 0.0f;
        g_sums[n * Hh + 128 + c] = 0.0f;
        if (c == 0) g_cnt[n] = 0.0f;
    }
    const float* src = (WHICH == 0) ? in : g_h1;
    float v = src[n * Cc + c];
    float s = v, s2 = v * v;
    #pragma unroll
    for (int o = 16; o; o >>= 1) {
        s  += __shfl_xor_sync(0xffffffffu, s,  o);
        s2 += __shfl_xor_sync(0xffffffffu, s2, o);
    }
    __shared__ float ws[4], ws2[4];
    if ((c & 31) == 0) { ws[c >> 5] = s; ws2[c >> 5] = s2; }
    __syncthreads();
    s  = ws[0]  + ws[1]  + ws[2]  + ws[3];
    s2 = ws2[0] + ws2[1] + ws2[2] + ws2[3];
    float mu  = s * (1.0f / Cc);
    float var = s2 * (1.0f / Cc) - mu * mu;
    float o = (v - mu) * rsqrtf(var + kEps) * gg[c] + bb[c];
    if (WHICH == 0) {
        g_hn[n * Cc + c]    = o;
        g_hn_tf[n * Cc + c] = f2tf32(o);
    } else {
        g_h2_tf[n * Cc + c] = f2tf32(o);
    }
}

// ---------------- m_aggr -> tf32 ----------------
__global__ void magg_kernel() {
    int n = blockIdx.x, k = threadIdx.x;
    float inv = 1.0f / fmaxf(g_cnt[n], 1.0f);
    g_ma_tf[n * Hh + k] = f2tf32(g_sums[n * Hh + k] * inv);
}

// ---------------- generic node GEMM on mma.sync tf32 ----------------
enum { M_P1P2 = 0, M_NMLP1 = 1, M_NMLP2 = 2, M_MMLP1 = 3, M_MMLP2 = 4 };
#define BSTN 136   // B smem row stride (u32)

template<int K, int NCOLS, int MODE>
__global__ void __launch_bounds__(256) node_gemm(const float* __restrict__ bias,
                                                 const float* __restrict__ res1,
                                                 float* __restrict__ out_h) {
    const uint32_t* A0;  const uint32_t* A1 = nullptr;
    const uint32_t* Btf; float* outf = nullptr; uint32_t* outu = nullptr;
    if constexpr (MODE == M_P1P2)  { A0 = g_hn_tf; Btf = g_We1tf; outf = g_P12; }
    if constexpr (MODE == M_NMLP1) { A0 = g_hn_tf; A1 = g_ma_tf; Btf = g_Wn1tf; outu = g_t; }
    if constexpr (MODE == M_NMLP2) { A0 = g_t;     Btf = g_Wn2tf; outf = g_h1; }
    if constexpr (MODE == M_MMLP1) { A0 = g_h2_tf; Btf = g_Wm1tf; outu = g_u; }
    if constexpr (MODE == M_MMLP2) { A0 = g_u;     Btf = g_Wm2tf; outf = out_h; }
    constexpr int KA0 = (MODE == M_NMLP1) ? 128 : K;
    constexpr int NCH = K / 16;

    __shared__ __align__(16) uint32_t Bs[2][16 * BSTN];
    int tid = threadIdx.x, lane = tid & 31, w = tid >> 5;
    int wm = w & 1, wn = w >> 1;
    int rbase = blockIdx.x * 64;
    int cbase = blockIdx.y * 128;
    uint32_t sB[2] = { (uint32_t)__cvta_generic_to_shared(Bs[0]),
                       (uint32_t)__cvta_generic_to_shared(Bs[1]) };

    #pragma unroll
    for (int i = 0; i < 2; i++) {
        int idx4 = tid + i * 256;
        int k = idx4 >> 5, n4 = (idx4 & 31) << 2;
        cp_async16(sB[0] + (k * BSTN + n4) * 4, Btf + k * NCOLS + cbase + n4);
    }
    asm volatile("cp.async.commit_group;\n\tcp.async.wait_group 0;" ::: "memory");
    __syncthreads();

    float acc[2][4][4];
    #pragma unroll
    for (int mt = 0; mt < 2; mt++)
        #pragma unroll
        for (int nt = 0; nt < 4; nt++)
            #pragma unroll
            for (int q = 0; q < 4; q++) acc[mt][nt][q] = 0.0f;

    int rc[2][2];
    #pragma unroll
    for (int mt = 0; mt < 2; mt++) {
        rc[mt][0] = min(rbase + 32 * wm + 16 * mt + (lane >> 2), Nn - 1);
        rc[mt][1] = min(rbase + 32 * wm + 16 * mt + (lane >> 2) + 8, Nn - 1);
    }
    int bq = 32 * wn + (lane >> 2);

    #pragma unroll 1
    for (int kc = 0; kc < NCH; kc++) {
        if (kc < NCH - 1) {
            const uint32_t* src = Btf + (kc + 1) * 16 * NCOLS + cbase;
            uint32_t d = sB[(kc + 1) & 1];
            #pragma unroll
            for (int i = 0; i < 2; i++) {
                int idx4 = tid + i * 256;
                int k = idx4 >> 5, n4 = (idx4 & 31) << 2;
                cp_async16(d + (k * BSTN + n4) * 4, src + k * NCOLS + n4);
            }
            asm volatile("cp.async.commit_group;" ::: "memory");
        }
        const uint32_t* Bw = Bs[kc & 1] + (lane & 3) * BSTN + bq;
        #pragma unroll
        for (int st = 0; st < 2; st++) {
            int kk = kc * 16 + st * 8 + (lane & 3);
            uint32_t a[2][4];
            #pragma unroll
            for (int mt = 0; mt < 2; mt++) {
                const uint32_t *pa0, *pa1;
                if (MODE == M_NMLP1 && kk >= 128) {
                    pa0 = A1 + rc[mt][0] * Hh + (kk - 128);
                    pa1 = A1 + rc[mt][1] * Hh + (kk - 128);
                } else {
                    pa0 = A0 + rc[mt][0] * KA0 + kk;
                    pa1 = A0 + rc[mt][1] * KA0 + kk;
                }
                a[mt][0] = pa0[0]; a[mt][1] = pa1[0];
                a[mt][2] = pa0[4]; a[mt][3] = pa1[4];
            }
            uint32_t b[4][2];
            const uint32_t* Bb = Bw + st * 8 * BSTN;
            #pragma unroll
            for (int nt = 0; nt < 4; nt++) {
                b[nt][0] = Bb[8 * nt];
                b[nt][1] = Bb[4 * BSTN + 8 * nt];
            }
            #pragma unroll
            for (int mt = 0; mt < 2; mt++)
                #pragma unroll
                for (int nt = 0; nt < 4; nt++)
                    mma_tf32(acc[mt][nt][0], acc[mt][nt][1], acc[mt][nt][2], acc[mt][nt][3],
                             a[mt][0], a[mt][1], a[mt][2], a[mt][3], b[nt][0], b[nt][1]);
        }
        if (kc < NCH - 1) asm volatile("cp.async.wait_group 0;" ::: "memory");
        __syncthreads();
    }

    #pragma unroll
    for (int mt = 0; mt < 2; mt++) {
        int r0 = rbase + 32 * wm + 16 * mt + (lane >> 2);
        int r1r = r0 + 8;
        #pragma unroll
        for (int nt = 0; nt < 4; nt++) {
            int col = cbase + 32 * wn + 8 * nt + 2 * (lane & 3);
            #pragma unroll
            for (int q = 0; q < 4; q++) {
                int r  = (q < 2) ? r0 : r1r;
                int cg = col + (q & 1);
                if (r < Nn) {
                    float v = acc[mt][nt][q];
                    if constexpr (MODE == M_P1P2) {
                        outf[r * NCOLS + cg] = v;
                    } else if constexpr (MODE == M_NMLP1 || MODE == M_MMLP1) {
                        outu[r * NCOLS + cg] = f2tf32(silu_f(v + bias[cg]));
                    } else if constexpr (MODE == M_NMLP2) {
                        outf[r * NCOLS + cg] = res1[r * NCOLS + cg] + g_hn[r * NCOLS + cg]
                                             + v + bias[cg];
                    } else {   // M_MMLP2
                        outf[r * NCOLS + cg] = g_h1[r * NCOLS + cg] + v + bias[cg];
                    }
                }
            }
        }
    }
}

// ---------------- edge kernel: pair-interleaved smem + LDS.64 frags + pipelined mainloop ----
#define EPB  64                 // edges per CTA (GEMM M)
#define KC   16                 // K-chunk rows
#define ASTA 264                // A smem row stride (u32), 264 % 32 == 8
#define BSTB 520                // B smem kq-row stride (u32), 520 % 32 == 8
constexpr int A_SMEM_U32 = EPB * ASTA;       // 16896
constexpr int B_SMEM_U32 = 8 * BSTB;         // 4160 per chunk buffer
constexpr int EDGE_DSMEM = (A_SMEM_U32 + 2 * B_SMEM_U32) * 4;   // 100864 B

__global__ void __launch_bounds__(256, 2) edge_kernel(const float* __restrict__ x,
                                                      const int*   __restrict__ eidx,
                                                      const float* __restrict__ We1,
                                                      const float* __restrict__ be1,
                                                      const float* __restrict__ be2) {
    extern __shared__ __align__(16) uint32_t dynbuf[];
    uint32_t* As = dynbuf;                         // [64][ASTA] pair-interleaved
    uint32_t* Bs[2] = { dynbuf + A_SMEM_U32,
                        dynbuf + A_SMEM_U32 + B_SMEM_U32 };

    __shared__ float sDist[EPB], sCcut[EPB], sWl[Hh], sBe1[Hh], sBe2[Hh];
    __shared__ int   sRow[EPB], sCol[EPB];

    int tid  = threadIdx.x;
    int lane = tid & 31;
    int w    = tid >> 5;
    int wm   = w & 1;
    int wn   = w >> 1;
    int e0   = blockIdx.x * EPB;

    uint32_t sBu[2];
    sBu[0] = (uint32_t)__cvta_generic_to_shared(Bs[0]);
    sBu[1] = (uint32_t)__cvta_generic_to_shared(Bs[1]);

    // stage B chunk 0 (pair-permuted global layout; 8 rows x 512 u32)
    {
        #pragma unroll
        for (int i = 0; i < 4; i++) {
            int idx4 = tid + i * 256;          // 0..1023
            int rr   = idx4 >> 7;              // 0..7
            int off4 = idx4 & 127;
            cp_async16(sBu[0] + (rr * BSTB + off4 * 4) * 4,
                       g_We2p + rr * 512 + off4 * 4);
        }
        asm volatile("cp.async.commit_group;" ::: "memory");
    }

    if (tid < EPB) {
        int e = e0 + tid;
        int r = eidx[e];
        int c = eidx[Ee + e];
        sRow[tid] = r;
        sCol[tid] = c;
        float dx = x[r * 3 + 0] - x[c * 3 + 0];
        float dy = x[r * 3 + 1] - x[c * 3 + 1];
        float dz = x[r * 3 + 2] - x[c * 3 + 2];
        float d  = sqrtf(dx * dx + dy * dy + dz * dz);
        sDist[tid] = d;
        float cc = 0.5f * (__cosf(d * (kPi / kCutoff)) + 1.0f);
        sCcut[tid] = (d <= kCutoff) ? cc : 0.0f;
        atomicAdd(&g_cnt[c], 1.0f);
    }
    sWl[tid]  = We1[(2 * Cc) * Hh + tid];
    sBe1[tid] = be1[tid];
    sBe2[tid] = be2[tid];
    __syncthreads();

    // ---- A tile: silu(P1[row]+P2[col]+d*wl+b1) -> tf32, pair-interleaved:
    // lane owns cols 8L..8L+7; smem[e*ASTA + L*8 + (c&3)*2 + ((c>>2)&1)]
    #pragma unroll 2
    for (int ei = 0; ei < 8; ei++) {
        int e = w * 8 + ei;
        float d = sDist[e];
        const float4* p1 = (const float4*)(g_P12 + sRow[e] * 512);
        const float4* p2 = (const float4*)(g_P12 + sCol[e] * 512 + 256);
        float4 x0 = p1[2 * lane], x1 = p1[2 * lane + 1];
        float4 y0 = p2[2 * lane], y1 = p2[2 * lane + 1];
        float4 w0 = ((const float4*)sWl)[2 * lane],  w1 = ((const float4*)sWl)[2 * lane + 1];
        float4 c0 = ((const float4*)sBe1)[2 * lane], c1 = ((const float4*)sBe1)[2 * lane + 1];
        uint4 o0, o1;
        o0.x = f2tf32(silu_f(x0.x + y0.x + d * w0.x + c0.x));   // col+0
        o0.y = f2tf32(silu_f(x1.x + y1.x + d * w1.x + c1.x));   // col+4
        o0.z = f2tf32(silu_f(x0.y + y0.y + d * w0.y + c0.y));   // col+1
        o0.w = f2tf32(silu_f(x1.y + y1.y + d * w1.y + c1.y));   // col+5
        o1.x = f2tf32(silu_f(x0.z + y0.z + d * w0.z + c0.z));   // col+2
        o1.y = f2tf32(silu_f(x1.z + y1.z + d * w1.z + c1.z));   // col+6
        o1.z = f2tf32(silu_f(x0.w + y0.w + d * w0.w + c0.w));   // col+3
        o1.w = f2tf32(silu_f(x1.w + y1.w + d * w1.w + c1.w));   // col+7
        *(uint4*)(As + e * ASTA + lane * 8)     = o0;
        *(uint4*)(As + e * ASTA + lane * 8 + 4) = o1;
    }
    asm volatile("cp.async.wait_group 0;" ::: "memory");
    __syncthreads();

    float acc[2][8][4];
    #pragma unroll
    for (int mt = 0; mt < 2; mt++)
        #pragma unroll
        for (int nt = 0; nt < 8; nt++)
            #pragma unroll
            for (int q = 0; q < 4; q++) acc[mt][nt][q] = 0.0f;

    int ar0 = 32 * wm + (lane >> 2);
    int bq0 = 64 * wn + (lane >> 2);
    const uint32_t* Aw = As + ar0 * ASTA + (lane & 3) * 2;

    uint2 bf0[8], bf1[8];

    // B frag load: pair (k, k+4) adjacent; row = st*4 + (lane&3)
    #define LDB(bf, buf, st)                                                     \
        {                                                                        \
            const uint32_t* p_ = Bs[buf] + ((st) * 4 + (lane & 3)) * BSTB + bq0 * 2; \
            _Pragma("unroll")                                                    \
            for (int nt_ = 0; nt_ < 8; nt_++)                                    \
                bf[nt_] = *(const uint2*)(p_ + nt_ * 16);                        \
        }

    #define LDA_MMA(bf, kc, st)                                                  \
        {                                                                        \
            const uint32_t* Ab_ = Aw + ((kc) * 2 + (st)) * 8;                    \
            uint2 a00 = *(const uint2*)(Ab_);                                    \
            uint2 a01 = *(const uint2*)(Ab_ + 8 * ASTA);                         \
            uint2 a10 = *(const uint2*)(Ab_ + 16 * ASTA);                        \
            uint2 a11 = *(const uint2*)(Ab_ + 24 * ASTA);                        \
            _Pragma("unroll")                                                    \
            for (int nt_ = 0; nt_ < 8; nt_++) {                                  \
                mma_tf32(acc[0][nt_][0], acc[0][nt_][1], acc[0][nt_][2], acc[0][nt_][3], \
                         a00.x, a01.x, a00.y, a01.y, bf[nt_].x, bf[nt_].y);      \
                mma_tf32(acc[1][nt_][0], acc[1][nt_][1], acc[1][nt_][2], acc[1][nt_][3], \
                         a10.x, a11.x, a10.y, a11.y, bf[nt_].x, bf[nt_].y);      \
            }                                                                    \
        }

    LDB(bf0, 0, 0);
    #pragma unroll 1
    for (int kc = 0; kc < 16; kc++) {
        if (kc < 15) {
            const uint32_t* src = g_We2p + (kc + 1) * 4096;
            uint32_t dstb = sBu[(kc + 1) & 1];
            #pragma unroll
            for (int i = 0; i < 4; i++) {
                int idx4 = tid + i * 256;
                int rr   = idx4 >> 7;
                int off4 = idx4 & 127;
                cp_async16(dstb + (rr * BSTB + off4 * 4) * 4, src + rr * 512 + off4 * 4);
            }
            asm volatile("cp.async.commit_group;" ::: "memory");
        }
        LDB(bf1, kc & 1, 1);
        LDA_MMA(bf0, kc, 0);
        if (kc < 15) asm volatile("cp.async.wait_group 0;" ::: "memory");
        __syncthreads();
        if (kc < 15) LDB(bf0, (kc + 1) & 1, 0);
        LDA_MMA(bf1, kc, 1);
    }

    // ---- epilogue: +bias, silu, *cutoff, scatter-add
    #pragma unroll
    for (int mt = 0; mt < 2; mt++) {
        int r0 = 32 * wm + 16 * mt + (lane >> 2);
        int r1 = r0 + 8;
        float cc0 = sCcut[r0], cc1 = sCcut[r1];
        int base0 = sCol[r0] * Hh, base1 = sCol[r1] * Hh;
        #pragma unroll
        for (int nt = 0; nt < 8; nt++) {
            int col = 64 * wn + 8 * nt + 2 * (lane & 3);
            float b0 = sBe2[col], b1 = sBe2[col + 1];
            atomicAdd(&g_sums[base0 + col],     silu_f(acc[0 + mt * 0][nt][0] * 0.0f + acc[mt][nt][0] + b0) * cc0);
            atomicAdd(&g_sums[base0 + col + 1], silu_f(acc[mt][nt][1] + b1) * cc0);
            atomicAdd(&g_sums[base1 + col],     silu_f(acc[mt][nt][2] + b0) * cc1);
            atomicAdd(&g_sums[base1 + col + 1], silu_f(acc[mt][nt][3] + b1) * cc1);
        }
    }
}

// ---------------- launch ----------------
extern "C" void kernel_launch(void* const* d_in, const int* in_sizes, int n_in,
                              void* d_out, int out_size) {
    const float* x     = (const float*)d_in[0];
    const float* h     = (const float*)d_in[1];
    const int*   eidx  = (const int*)  d_in[2];
    const float* We1   = (const float*)d_in[3];
    const float* be1   = (const float*)d_in[4];
    const float* We2   = (const float*)d_in[5];
    const float* be2   = (const float*)d_in[6];
    const float* Wn1   = (const float*)d_in[7];
    const float* bn1   = (const float*)d_in[8];
    const float* Wn2   = (const float*)d_in[9];
    const float* bn2   = (const float*)d_in[10];
    const float* Wm1   = (const float*)d_in[11];
    const float* bm1   = (const float*)d_in[12];
    const float* Wm2   = (const float*)d_in[13];
    const float* bm2   = (const float*)d_in[14];
    const float* g1    = (const float*)d_in[15];
    const float* beta1 = (const float*)d_in[16];
    const float* g2    = (const float*)d_in[17];
    const float* beta2 = (const float*)d_in[18];

    static int attr_done = 0;
    if (!attr_done) {
        cudaFuncSetAttribute(edge_kernel,
                             cudaFuncAttributeMaxDynamicSharedMemorySize, EDGE_DSMEM);
        attr_done = 1;
    }

    const int RB = (Nn + 63) / 64;   // 157

    // NOTE: edge_kernel is intentionally launch #4 (ncu samples the 4th launch).
    prepW_kernel<<<((Cc + Hh) * Hh + 255) / 256, 256>>>(We2, Wn1, Wn2, Wm1, Wm2, We1);
    ln_kernel<0><<<Nn, Cc>>>(h, g1, beta1);                               // also zeroes sums/cnt
    node_gemm<128, 512, M_P1P2><<<dim3(RB, 4), 256>>>(nullptr, nullptr, nullptr);
    edge_kernel<<<Ee / EPB, 256, EDGE_DSMEM>>>(x, eidx, We1, be1, be2);
    magg_kernel<<<Nn, Hh>>>();
    node_gemm<384, 256, M_NMLP1><<<dim3(RB, 2), 256>>>(bn1, nullptr, nullptr);
    node_gemm<256, 128, M_NMLP2><<<dim3(RB, 1), 256>>>(bn2, h, nullptr);
    ln_kernel<1><<<Nn, Cc>>>(h, g2, beta2);
    node_gemm<128, 256, M_MMLP1><<<dim3(RB, 2), 256>>>(bm1, nullptr, nullptr);
    node_gemm<256, 128, M_MMLP2><<<dim3(RB, 1), 256>>>(bm2, nullptr, (float*)d_out);
}